// round 9
// baseline (speedup 1.0000x reference)
#include <cuda_runtime.h>
#include <cuda_bf16.h>
#include <math.h>

#define NN 4096
#define KN 48
#define CC 128
#define EC 384
#define HD 512

// ---------------- scratch (device globals: allocation-free) ----------------
__device__ float g_node_pre[NN * CC];   // node @ W1a^T + b_m1
__device__ float g_S[NN * CC];          // sum_k attn * h2
__device__ float g_A[NN];               // sum_k attn
__device__ unsigned g_Wp1T[128 * 192];  // W1b packed bf16x2, n-major: [c][kk]
__device__ unsigned g_Wp2T[128 * 64];   // W2  packed bf16x2, n-major: [c][kk]

__device__ __forceinline__ float gelu_f(float x) {
    return 0.5f * x * (1.0f + erff(x * 0.70710678118654752440f));
}

__device__ __forceinline__ unsigned pk(float a, float b) {
    __nv_bfloat162 t = __floats2bfloat162_rn(a, b);
    return *(unsigned*)&t;
}

__device__ __forceinline__ void mma_bf16(float c[4], const unsigned a[4], const unsigned b[2]) {
    asm volatile(
        "mma.sync.aligned.m16n8k16.row.col.f32.bf16.bf16.f32 "
        "{%0,%1,%2,%3},{%4,%5,%6,%7},{%8,%9},{%0,%1,%2,%3};\n"
        : "+f"(c[0]), "+f"(c[1]), "+f"(c[2]), "+f"(c[3])
        : "r"(a[0]), "r"(a[1]), "r"(a[2]), "r"(a[3]), "r"(b[0]), "r"(b[1]));
}

__device__ __forceinline__ void ldsm4(unsigned r[4], unsigned addr) {
    asm volatile("ldmatrix.sync.aligned.m8n8.x4.shared.b16 {%0,%1,%2,%3}, [%4];"
                 : "=r"(r[0]), "=r"(r[1]), "=r"(r[2]), "=r"(r[3]) : "r"(addr));
}

#define CP_ASYNC16(dst, src) \
    asm volatile("cp.async.cg.shared.global [%0], [%1], 16;" :: "r"(dst), "l"(src))
#define CP_COMMIT() asm volatile("cp.async.commit_group;" ::)
#define CP_WAIT0()  asm volatile("cp.async.wait_group 0;" ::)

// =================== Kprep: pack weights to bf16x2 (n-major) ===============
__global__ __launch_bounds__(256)
void k_prep(const float* __restrict__ W1, const float* __restrict__ W2) {
    int idx = blockIdx.x * 256 + threadIdx.x;
    if (idx < 128 * 192) {
        int c = idx / 192, kk = idx % 192;
        g_Wp1T[idx] = pk(W1[(size_t)c * 512 + 128 + 2 * kk],
                         W1[(size_t)c * 512 + 128 + 2 * kk + 1]);
    } else if (idx < 128 * 192 + 128 * 64) {
        int j = idx - 128 * 192;
        int c = j >> 6, kk = j & 63;
        g_Wp2T[j] = pk(W2[(size_t)c * 128 + 2 * kk],
                       W2[(size_t)c * 128 + 2 * kk + 1]);
    }
}

// ======================= K0: node_pre = node @ W1a^T + b1 ==================
__global__ __launch_bounds__(256)
void k0_node_pre(const float* __restrict__ node, const float* __restrict__ W1,
                 const float* __restrict__ b1) {
    extern __shared__ float sm[];
    float* sX = sm;           // 32*128
    float* sW = sm + 4096;    // 128*128  sW[k][c] = W1[c*512 + k]
    const int tid = threadIdx.x, tx = tid & 15, ty = tid >> 4;
    const int n0 = blockIdx.x * 32;

#pragma unroll
    for (int m = 0; m < 4; ++m) {
        int f4 = tid + 256 * m;
        int r = f4 >> 5, c4 = f4 & 31;
        *(float4*)(sX + r * 128 + c4 * 4) =
            *(const float4*)(node + (size_t)(n0 + r) * 128 + c4 * 4);
    }
#pragma unroll
    for (int m = 0; m < 16; ++m) {
        int idx = tid + 256 * m;
        int c = idx & 127, k4 = idx >> 7;
        float4 v = *(const float4*)(W1 + (size_t)c * 512 + k4 * 4);
        sW[(k4 * 4 + 0) * 128 + c] = v.x;
        sW[(k4 * 4 + 1) * 128 + c] = v.y;
        sW[(k4 * 4 + 2) * 128 + c] = v.z;
        sW[(k4 * 4 + 3) * 128 + c] = v.w;
    }
    __syncthreads();

    float acc[2][8] = {};
#pragma unroll
    for (int kk = 0; kk < 128; kk += 4) {
        float a[2][4];
#pragma unroll
        for (int i = 0; i < 2; ++i) {
            float4 t = *(float4*)(sX + (ty + 16 * i) * 128 + kk);
            a[i][0] = t.x; a[i][1] = t.y; a[i][2] = t.z; a[i][3] = t.w;
        }
#pragma unroll
        for (int q = 0; q < 4; ++q) {
            float4 b0 = *(float4*)(sW + (kk + q) * 128 + tx * 8);
            float4 b1v = *(float4*)(sW + (kk + q) * 128 + tx * 8 + 4);
            float bb[8] = {b0.x, b0.y, b0.z, b0.w, b1v.x, b1v.y, b1v.z, b1v.w};
#pragma unroll
            for (int i = 0; i < 2; ++i)
#pragma unroll
                for (int j = 0; j < 8; ++j) acc[i][j] += a[i][q] * bb[j];
        }
    }
#pragma unroll
    for (int i = 0; i < 2; ++i) {
        int r = n0 + ty + 16 * i;
#pragma unroll
        for (int j = 0; j < 8; ++j) {
            int c = tx * 8 + j;
            g_node_pre[(size_t)r * 128 + c] = acc[i][j] + b1[c];
        }
    }
}

// ================ K1: per-node-pair edge message kernel (bf16 MMA) =========
// 2 nodes/block, 8 warps = mg(2) x ng(4). ldmatrix fragments, double-buffered
// k-tiles (register-staged A + cp.async B).
// smem words (u32): A dbuf [96x36]x2 @0/@3456; B dbuf [128x36]x2 @6912/@11520
// After GEMM1: sH [96x68] @0 ; sW2 [128x68] @6912. misc @16128.
#define W_SA0 0
#define W_SA1 3456
#define W_SB0 6912
#define W_SB1 11520
#define W_SH  0
#define W_SW2 6912
#define W_NP  16128
#define W_AT  16384
#define W_B2  16512
#define S1_WORDS 16640

__global__ __launch_bounds__(256, 2)
void k1_edges(const float* __restrict__ edge, const float* __restrict__ attn,
              const float* __restrict__ b2) {
    extern __shared__ unsigned smu[];
    float* sNP = (float*)(smu + W_NP);
    float* sAt = (float*)(smu + W_AT);
    float* sb2 = (float*)(smu + W_B2);

    const int tid = threadIdx.x;
    const int lane = tid & 31, wid = tid >> 5;
    const int mg = wid >> 2;
    const int ng = wid & 3;
    const int g = lane >> 2, q = lane & 3;
    const int n0 = blockIdx.x * 2;
    const float* eb = edge + (size_t)n0 * (KN * EC);
    const unsigned smem_base = (unsigned)__cvta_generic_to_shared(smu);

    sNP[tid] = g_node_pre[(size_t)n0 * 128 + tid];
    if (tid < 96) sAt[tid] = attn[(size_t)n0 * KN + tid];
    if (tid < 128) sb2[tid] = b2[tid];

    // ---- prologue: tile 0 into buf0 ----
#pragma unroll
    for (int m = 0; m < 6; ++m) {
        int f = tid + 256 * m;
        int row = f >> 4, c4 = f & 15;
        float4 v = *(const float4*)(eb + (size_t)row * EC + c4 * 4);
        *(uint2*)(smu + W_SA0 + row * 36 + c4 * 2) =
            make_uint2(pk(v.x, v.y), pk(v.z, v.w));
    }
#pragma unroll
    for (int m = 0; m < 4; ++m) {
        int f = tid + 256 * m;
        int row = f >> 3, j = f & 7;
        CP_ASYNC16(smem_base + (W_SB0 + row * 36 + j * 4) * 4,
                   g_Wp1T + (size_t)row * 192 + j * 4);
    }
    CP_COMMIT();
    CP_WAIT0();
    __syncthreads();

    // ---- fragment base addresses (bytes) ----
    const unsigned aB = smem_base + (mg * 48 + (lane & 15)) * 144 + (lane >> 4) * 16;
    const unsigned bB = smem_base + W_SB0 * 4 +
                        (ng * 32 + (lane & 7) + (lane >> 4) * 8) * 144 +
                        ((lane >> 3) & 1) * 16;

    float acc[3][4][4] = {};
    float4 st[6];

    // ---------------- GEMM1b over edge context: 6 k-tiles of 64 ------------
    for (int kt = 0; kt < 6; ++kt) {
        if (kt < 5) {
#pragma unroll
            for (int m = 0; m < 6; ++m) {
                int f = tid + 256 * m;
                int row = f >> 4, c4 = f & 15;
                st[m] = *(const float4*)(eb + (size_t)row * EC + (kt + 1) * 64 + c4 * 4);
            }
            unsigned dstB = smem_base + (((kt + 1) & 1) ? W_SB1 : W_SB0) * 4;
#pragma unroll
            for (int m = 0; m < 4; ++m) {
                int f = tid + 256 * m;
                int row = f >> 3, j = f & 7;
                CP_ASYNC16(dstB + row * 144 + j * 16,
                           g_Wp1T + (size_t)row * 192 + (kt + 1) * 32 + j * 4);
            }
            CP_COMMIT();
        }
        const unsigned aO = aB + (kt & 1) * 13824;
        const unsigned bO = bB + (kt & 1) * 18432;
#pragma unroll
        for (int s = 0; s < 4; ++s) {
            unsigned a0[4], a1[4], a2[4], bx[4], by[4];
            ldsm4(a0, aO + s * 32);
            ldsm4(a1, aO + 2304 + s * 32);
            ldsm4(a2, aO + 4608 + s * 32);
            ldsm4(bx, bO + s * 32);
            ldsm4(by, bO + 2304 + s * 32);
            mma_bf16(acc[0][0], a0, &bx[0]); mma_bf16(acc[0][1], a0, &bx[2]);
            mma_bf16(acc[0][2], a0, &by[0]); mma_bf16(acc[0][3], a0, &by[2]);
            mma_bf16(acc[1][0], a1, &bx[0]); mma_bf16(acc[1][1], a1, &bx[2]);
            mma_bf16(acc[1][2], a1, &by[0]); mma_bf16(acc[1][3], a1, &by[2]);
            mma_bf16(acc[2][0], a2, &bx[0]); mma_bf16(acc[2][1], a2, &bx[2]);
            mma_bf16(acc[2][2], a2, &by[0]); mma_bf16(acc[2][3], a2, &by[2]);
        }
        if (kt < 5) {
            unsigned* dA = smu + (((kt + 1) & 1) ? W_SA1 : W_SA0);
#pragma unroll
            for (int m = 0; m < 6; ++m) {
                int f = tid + 256 * m;
                int row = f >> 4, c4 = f & 15;
                *(uint2*)(dA + row * 36 + c4 * 2) =
                    make_uint2(pk(st[m].x, st[m].y), pk(st[m].z, st[m].w));
            }
            CP_WAIT0();
        }
        __syncthreads();
    }

    // ---- epilogue 1: h1 = gelu(node_pre + acc) -> sH; kick W2 copy --------
#pragma unroll
    for (int mi = 0; mi < 3; ++mi) {
        int r0 = mg * 48 + mi * 16 + g;
#pragma unroll
        for (int t = 0; t < 4; ++t) {
            int c = ng * 32 + t * 8 + 2 * q;
            float np0 = sNP[mg * 128 + c], np1 = sNP[mg * 128 + c + 1];
            unsigned lo = pk(gelu_f(acc[mi][t][0] + np0), gelu_f(acc[mi][t][1] + np1));
            unsigned hi = pk(gelu_f(acc[mi][t][2] + np0), gelu_f(acc[mi][t][3] + np1));
            smu[W_SH + r0 * 68 + ng * 16 + t * 4 + q] = lo;
            smu[W_SH + (r0 + 8) * 68 + ng * 16 + t * 4 + q] = hi;
            acc[mi][t][0] = acc[mi][t][1] = acc[mi][t][2] = acc[mi][t][3] = 0.f;
        }
    }
#pragma unroll
    for (int m = 0; m < 8; ++m) {
        int f = tid + 256 * m;
        int row = f >> 4, j = f & 15;
        CP_ASYNC16(smem_base + (W_SW2 + row * 68 + j * 4) * 4,
                   g_Wp2T + (size_t)row * 64 + j * 4);
    }
    CP_COMMIT();
    if (tid < 2) {
        float s = 0.f;
#pragma unroll
        for (int k = 0; k < KN; ++k) s += sAt[tid * KN + k];
        g_A[n0 + tid] = s;
    }
    CP_WAIT0();
    __syncthreads();

    // ---------------- GEMM2: h1 @ W2^T (8 k16 steps) -----------------------
    const unsigned a2B = smem_base + W_SH * 4 +
                         (mg * 48 + (lane & 15)) * 272 + (lane >> 4) * 16;
    const unsigned b2B = smem_base + W_SW2 * 4 +
                         (ng * 32 + (lane & 7) + (lane >> 4) * 8) * 272 +
                         ((lane >> 3) & 1) * 16;
#pragma unroll
    for (int s = 0; s < 8; ++s) {
        unsigned a0[4], a1[4], a2[4], bx[4], by[4];
        ldsm4(a0, a2B + s * 32);
        ldsm4(a1, a2B + 4352 + s * 32);
        ldsm4(a2, a2B + 8704 + s * 32);
        ldsm4(bx, b2B + s * 32);
        ldsm4(by, b2B + 4352 + s * 32);
        mma_bf16(acc[0][0], a0, &bx[0]); mma_bf16(acc[0][1], a0, &bx[2]);
        mma_bf16(acc[0][2], a0, &by[0]); mma_bf16(acc[0][3], a0, &by[2]);
        mma_bf16(acc[1][0], a1, &bx[0]); mma_bf16(acc[1][1], a1, &bx[2]);
        mma_bf16(acc[1][2], a1, &by[0]); mma_bf16(acc[1][3], a1, &by[2]);
        mma_bf16(acc[2][0], a2, &bx[0]); mma_bf16(acc[2][1], a2, &bx[2]);
        mma_bf16(acc[2][2], a2, &by[0]); mma_bf16(acc[2][3], a2, &by[2]);
    }

    // ---- epilogue 2: gelu(+b2), attn-weighted reduce over the 48 rows -----
#pragma unroll
    for (int t = 0; t < 4; ++t) {
        int c = ng * 32 + t * 8 + 2 * q;
        float bc0 = sb2[c], bc1 = sb2[c + 1];
        float p0 = 0.f, p1 = 0.f;
#pragma unroll
        for (int mi = 0; mi < 3; ++mi) {
            int r0 = mi * 16 + g;
            float w0 = sAt[mg * 48 + r0];
            float w1 = sAt[mg * 48 + r0 + 8];
            p0 += w0 * gelu_f(acc[mi][t][0] + bc0) + w1 * gelu_f(acc[mi][t][2] + bc0);
            p1 += w0 * gelu_f(acc[mi][t][1] + bc1) + w1 * gelu_f(acc[mi][t][3] + bc1);
        }
#pragma unroll
        for (int off = 16; off >= 4; off >>= 1) {
            p0 += __shfl_xor_sync(0xffffffffu, p0, off);
            p1 += __shfl_xor_sync(0xffffffffu, p1, off);
        }
        if (lane < 4) {
            int cc = ng * 32 + t * 8 + 2 * lane;
            g_S[(size_t)(n0 + mg) * 128 + cc] = p0;
            g_S[(size_t)(n0 + mg) * 128 + cc + 1] = p1;
        }
    }
}

// ====== K234: fused  x=LN1(node+(W3@S+A*b3)/30); H=gelu(x@Wd1^T+bd1);
//              out = mask*LN2(x + H@Wd2^T + bd2).   16 nodes/block ==========
#define T4_WORDS 27136
__global__ __launch_bounds__(256)
void k234(const float* __restrict__ node, const float* __restrict__ W3,
          const float* __restrict__ b3, const float* __restrict__ g1,
          const float* __restrict__ be1,
          const float* __restrict__ Wd1, const float* __restrict__ bd1,
          const float* __restrict__ Wd2, const float* __restrict__ bd2,
          const float* __restrict__ g2, const float* __restrict__ be2,
          const float* __restrict__ maskp, float* __restrict__ out) {
    extern __shared__ float sm[];
    float* sW = sm;            // 16384: current weight tile [k][c] (transposed)
    float* sX = sm + 16384;    // 2048: x (16 x 128)
    float* sH = sm + 18432;    // 8192: H (16 x 512); phase-A: S tile (16x128)
    float* sRs = sm + 26624;   // 256
    float* sRq = sm + 26880;   // 256
    const int tid = threadIdx.x, tx = tid & 15, ty = tid >> 4;
    const int n0 = blockIdx.x * 16;
    const int n = n0 + ty;

    // ---------------- phase A: x = LN1(node + (W3@S + A*b3)/30) ------------
#pragma unroll
    for (int m = 0; m < 2; ++m) {
        int f = tid + 256 * m;
        int r = f >> 5, c4 = f & 31;
        *(float4*)(sH + r * 128 + c4 * 4) =
            *(const float4*)(g_S + (size_t)(n0 + r) * 128 + c4 * 4);
    }
#pragma unroll
    for (int m = 0; m < 16; ++m) {
        int idx = tid + 256 * m;
        int d = idx & 127, c4 = idx >> 7;
        float4 v = *(const float4*)(W3 + (size_t)d * 128 + c4 * 4);
        sW[(c4 * 4 + 0) * 128 + d] = v.x;
        sW[(c4 * 4 + 1) * 128 + d] = v.y;
        sW[(c4 * 4 + 2) * 128 + d] = v.z;
        sW[(c4 * 4 + 3) * 128 + d] = v.w;
    }
    __syncthreads();

    float acc[8] = {};
#pragma unroll
    for (int kk = 0; kk < 128; kk += 4) {
        float4 t = *(float4*)(sH + ty * 128 + kk);
        float a[4] = {t.x, t.y, t.z, t.w};
#pragma unroll
        for (int qq = 0; qq < 4; ++qq) {
            float4 b0 = *(float4*)(sW + (kk + qq) * 128 + tx * 8);
            float4 b1 = *(float4*)(sW + (kk + qq) * 128 + tx * 8 + 4);
            float bb[8] = {b0.x, b0.y, b0.z, b0.w, b1.x, b1.y, b1.z, b1.w};
#pragma unroll
            for (int j = 0; j < 8; ++j) acc[j] += a[qq] * bb[j];
        }
    }

    float xv[8];
    {
        float As = g_A[n];
        float4 b30 = *(const float4*)(b3 + tx * 8);
        float4 b31 = *(const float4*)(b3 + tx * 8 + 4);
        float b3v[8] = {b30.x, b30.y, b30.z, b30.w, b31.x, b31.y, b31.z, b31.w};
        float4 nv0 = *(const float4*)(node + (size_t)n * 128 + tx * 8);
        float4 nv1 = *(const float4*)(node + (size_t)n * 128 + tx * 8 + 4);
        float nb[8] = {nv0.x, nv0.y, nv0.z, nv0.w, nv1.x, nv1.y, nv1.z, nv1.w};
        float s = 0.f, qs = 0.f;
#pragma unroll
        for (int j = 0; j < 8; ++j) {
            float v = nb[j] + (acc[j] + As * b3v[j]) * (1.0f / 30.0f);
            xv[j] = v; s += v; qs += v * v;
        }
        sRs[ty * 16 + tx] = s;
        sRq[ty * 16 + tx] = qs;
    }
    __syncthreads();
    {
        float s = 0.f, qs = 0.f;
#pragma unroll
        for (int t = 0; t < 16; ++t) { s += sRs[ty * 16 + t]; qs += sRq[ty * 16 + t]; }
        float mu = s * (1.0f / 128.0f);
        float var = qs * (1.0f / 128.0f) - mu * mu;
        float rs = rsqrtf(var + 1e-5f);
        float4 ga = *(const float4*)(g1 + tx * 8);
        float4 gb = *(const float4*)(g1 + tx * 8 + 4);
        float4 ea = *(const float4*)(be1 + tx * 8);
        float4 eb2 = *(const float4*)(be1 + tx * 8 + 4);
        float gv[8] = {ga.x, ga.y, ga.z, ga.w, gb.x, gb.y, gb.z, gb.w};
        float ev[8] = {ea.x, ea.y, ea.z, ea.w, eb2.x, eb2.y, eb2.z, eb2.w};
#pragma unroll
        for (int j = 0; j < 8; ++j) xv[j] = (xv[j] - mu) * rs * gv[j] + ev[j];
        *(float4*)(sX + ty * 128 + tx * 8) = make_float4(xv[0], xv[1], xv[2], xv[3]);
        *(float4*)(sX + ty * 128 + tx * 8 + 4) = make_float4(xv[4], xv[5], xv[6], xv[7]);
    }
    __syncthreads();

    // ---------------- phase B: H = gelu(x @ Wd1^T + bd1) -------------------
    for (int t = 0; t < 4; ++t) {
        int h0 = t * 128;
#pragma unroll
        for (int m = 0; m < 16; ++m) {
            int idx = tid + 256 * m;
            int h = idx & 127, k4 = idx >> 7;
            float4 v = *(const float4*)(Wd1 + (size_t)(h0 + h) * 128 + k4 * 4);
            sW[(k4 * 4 + 0) * 128 + h] = v.x;
            sW[(k4 * 4 + 1) * 128 + h] = v.y;
            sW[(k4 * 4 + 2) * 128 + h] = v.z;
            sW[(k4 * 4 + 3) * 128 + h] = v.w;
        }
        __syncthreads();
        float a2[8] = {};
#pragma unroll
        for (int kk = 0; kk < 128; kk += 4) {
            float4 tt = *(float4*)(sX + ty * 128 + kk);
            float a[4] = {tt.x, tt.y, tt.z, tt.w};
#pragma unroll
            for (int qq = 0; qq < 4; ++qq) {
                float4 b0 = *(float4*)(sW + (kk + qq) * 128 + tx * 8);
                float4 b1 = *(float4*)(sW + (kk + qq) * 128 + tx * 8 + 4);
                float bb[8] = {b0.x, b0.y, b0.z, b0.w, b1.x, b1.y, b1.z, b1.w};
#pragma unroll
                for (int j = 0; j < 8; ++j) a2[j] += a[qq] * bb[j];
            }
        }
#pragma unroll
        for (int j = 0; j < 8; ++j) {
            int h = h0 + tx * 8 + j;
            sH[ty * 512 + h] = gelu_f(a2[j] + bd1[h]);
        }
        __syncthreads();
    }

    // ---------------- phase C: out = mask*LN2(x + H @ Wd2^T + bd2) ---------
    float acc3[8] = {};
    for (int t = 0; t < 4; ++t) {
        int k0 = t * 128;
#pragma unroll
        for (int m = 0; m < 16; ++m) {
            int idx = tid + 256 * m;
            int c = idx & 127, k4 = idx >> 7;
            float4 v = *(const float4*)(Wd2 + (size_t)c * 512 + k0 + k4 * 4);
            sW[(k4 * 4 + 0) * 128 + c] = v.x;
            sW[(k4 * 4 + 1) * 128 + c] = v.y;
            sW[(k4 * 4 + 2) * 128 + c] = v.z;
            sW[(k4 * 4 + 3) * 128 + c] = v.w;
        }
        __syncthreads();
#pragma unroll
        for (int kk = 0; kk < 128; kk += 4) {
            float4 tt = *(float4*)(sH + ty * 512 + k0 + kk);
            float a[4] = {tt.x, tt.y, tt.z, tt.w};
#pragma unroll
            for (int qq = 0; qq < 4; ++qq) {
                float4 b0 = *(float4*)(sW + (kk + qq) * 128 + tx * 8);
                float4 b1 = *(float4*)(sW + (kk + qq) * 128 + tx * 8 + 4);
                float bb[8] = {b0.x, b0.y, b0.z, b0.w, b1.x, b1.y, b1.z, b1.w};
#pragma unroll
                for (int j = 0; j < 8; ++j) acc3[j] += a[qq] * bb[j];
            }
        }
        __syncthreads();
    }

    {
        float4 ba = *(const float4*)(bd2 + tx * 8);
        float4 bbv = *(const float4*)(bd2 + tx * 8 + 4);
        float bdv[8] = {ba.x, ba.y, ba.z, ba.w, bbv.x, bbv.y, bbv.z, bbv.w};
        float4 x0 = *(float4*)(sX + ty * 128 + tx * 8);
        float4 x1 = *(float4*)(sX + ty * 128 + tx * 8 + 4);
        float xb[8] = {x0.x, x0.y, x0.z, x0.w, x1.x, x1.y, x1.z, x1.w};
        float vv[8];
        float s = 0.f, qs = 0.f;
#pragma unroll
        for (int j = 0; j < 8; ++j) {
            float v = xb[j] + acc3[j] + bdv[j];
            vv[j] = v; s += v; qs += v * v;
        }
        sRs[ty * 16 + tx] = s;
        sRq[ty * 16 + tx] = qs;
        __syncthreads();
        s = 0.f; qs = 0.f;
#pragma unroll
        for (int t = 0; t < 16; ++t) { s += sRs[ty * 16 + t]; qs += sRq[ty * 16 + t]; }
        float mu = s * (1.0f / 128.0f);
        float var = qs * (1.0f / 128.0f) - mu * mu;
        float rs = rsqrtf(var + 1e-5f);
        float mk = maskp[n];
        float4 ga = *(const float4*)(g2 + tx * 8);
        float4 gb = *(const float4*)(g2 + tx * 8 + 4);
        float4 ea = *(const float4*)(be2 + tx * 8);
        float4 eb2 = *(const float4*)(be2 + tx * 8 + 4);
        float gv[8] = {ga.x, ga.y, ga.z, ga.w, gb.x, gb.y, gb.z, gb.w};
        float ev[8] = {ea.x, ea.y, ea.z, ea.w, eb2.x, eb2.y, eb2.z, eb2.w};
        float o[8];
#pragma unroll
        for (int j = 0; j < 8; ++j)
            o[j] = mk * ((vv[j] - mu) * rs * gv[j] + ev[j]);
        *(float4*)(out + (size_t)n * 128 + tx * 8) = make_float4(o[0], o[1], o[2], o[3]);
        *(float4*)(out + (size_t)n * 128 + tx * 8 + 4) = make_float4(o[4], o[5], o[6], o[7]);
    }
}

// ============================== launch =====================================
extern "C" void kernel_launch(void* const* d_in, const int* in_sizes, int n_in,
                              void* d_out, int out_size) {
    const float* node = (const float*)d_in[0];
    const float* edge = (const float*)d_in[1];
    const float* mask = (const float*)d_in[2];
    const float* attn = (const float*)d_in[3];
    const float* W1   = (const float*)d_in[4];
    const float* b1   = (const float*)d_in[5];
    const float* W2   = (const float*)d_in[6];
    const float* b2   = (const float*)d_in[7];
    const float* W3   = (const float*)d_in[8];
    const float* b3   = (const float*)d_in[9];
    const float* g1   = (const float*)d_in[10];
    const float* be1  = (const float*)d_in[11];
    const float* Wd1  = (const float*)d_in[12];
    const float* bd1  = (const float*)d_in[13];
    const float* Wd2  = (const float*)d_in[14];
    const float* bd2  = (const float*)d_in[15];
    const float* g2   = (const float*)d_in[16];
    const float* be2  = (const float*)d_in[17];
    float* out = (float*)d_out;

    const size_t s0 = (size_t)(4096 + 16384) * sizeof(float);
    const size_t s1 = (size_t)S1_WORDS * sizeof(unsigned);
    const size_t s4 = (size_t)T4_WORDS * sizeof(float);

    cudaFuncSetAttribute(k0_node_pre, cudaFuncAttributeMaxDynamicSharedMemorySize, (int)s0);
    cudaFuncSetAttribute(k1_edges,    cudaFuncAttributeMaxDynamicSharedMemorySize, (int)s1);
    cudaFuncSetAttribute(k234,        cudaFuncAttributeMaxDynamicSharedMemorySize, (int)s4);

    k_prep<<<128, 256>>>(W1, W2);
    k0_node_pre<<<NN / 32, 256, s0>>>(node, W1, b1);
    k1_edges<<<NN / 2, 256, s1>>>(edge, attn, b2);
    k234<<<NN / 16, 256, s4>>>(node, W3, b3, g1, be1, Wd1, bd1,
                               Wd2, bd2, g2, be2, mask, out);
}